// round 2
// baseline (speedup 1.0000x reference)
#include <cuda_runtime.h>
#include <math.h>

// Problem constants (fixed shapes from reference)
#define BQ 4
#define LQ 4096
#define DQ 512
#define NQ 64
#define MQ (BQ * LQ)        // 16384 rows
#define CHQ 64              // chunk length
#define NCQ (LQ / CHQ)      // 64 chunks per batch
#define NBLK (BQ * NCQ)     // 256 (b,chunk) blocks

// -------- scratch (device globals; no allocation allowed) --------
__device__ float g_xp[(size_t)MQ * 1024];        // xproj output: x_bar cols [0,512), z cols [512,1024)
__device__ float g_Bm[(size_t)MQ * 64];          // B projection (rmsnormed in place)
__device__ float g_Cm[(size_t)MQ * 64];          // C projection (rmsnormed in place)
__device__ float g_ax[(size_t)MQ * 512];         // per-step multiplier a=exp(la); overwritten with cumulative decay
__device__ float g_Yb[(size_t)MQ * 512];         // y buffer (intra -> full y -> normed h)
__device__ float g_cs[(size_t)NBLK * 64 * 512];  // chunk states -> prev states (in place)
__device__ float g_dtot[(size_t)NBLK * 512];     // per-chunk total decay
__device__ float g_Ac[512];                      // A coefficient per channel

// ============================ tiled fp32 GEMM ============================
// C[M,N] = A[M,K](lda) * B[K,N](ldb) (+bias), with epilogue:
//   EPI 0: linear (+optional bias)
//   EPI 1: a = exp(clip(clip(softplus(acc+bias),1e-4,5) * Acoef[n], -18.4206807, 0))
template <int BM, int BN, int BK, int TM, int TN, int EPI>
__global__ void __launch_bounds__((BM / TM) * (BN / TN))
sgemm_k(const float* __restrict__ A, int lda,
        const float* __restrict__ Bw, int ldb,
        const float* __restrict__ bias,
        float* __restrict__ C, int ldc,
        int K, const float* __restrict__ extra)
{
    constexpr int THREADS = (BM / TM) * (BN / TN);
    __shared__ float As[BK][BM];
    __shared__ float Bs[BK][BN];

    const int tid  = threadIdx.x;
    const int tx   = tid % (BN / TN);
    const int ty   = tid / (BN / TN);
    const int row0 = blockIdx.y * BM;
    const int col0 = blockIdx.x * BN;

    // A loader: float4 along K
    constexpr int A_K4 = BK / 4;
    const int a_r = tid / A_K4;
    const int a_c = tid % A_K4;
    constexpr int A_ROWS_PER_ITER = THREADS / A_K4;
    // B loader: float4 along N
    constexpr int B_N4 = BN / 4;
    const int b_n = tid % B_N4;
    const int b_k = tid / B_N4;
    constexpr int B_K_PER_ITER = THREADS / B_N4;

    float acc[TM][TN] = {};

    for (int k0 = 0; k0 < K; k0 += BK) {
        #pragma unroll
        for (int rr = 0; rr < BM; rr += A_ROWS_PER_ITER) {
            float4 v = *(const float4*)&A[(size_t)(row0 + rr + a_r) * lda + k0 + a_c * 4];
            As[a_c * 4 + 0][rr + a_r] = v.x;
            As[a_c * 4 + 1][rr + a_r] = v.y;
            As[a_c * 4 + 2][rr + a_r] = v.z;
            As[a_c * 4 + 3][rr + a_r] = v.w;
        }
        #pragma unroll
        for (int kk = 0; kk < BK; kk += B_K_PER_ITER) {
            *(float4*)&Bs[kk + b_k][b_n * 4] =
                *(const float4*)&Bw[(size_t)(k0 + kk + b_k) * ldb + col0 + b_n * 4];
        }
        __syncthreads();

        #pragma unroll
        for (int kk = 0; kk < BK; kk++) {
            float a[TM], bvv[TN];
            #pragma unroll
            for (int i = 0; i < TM; i++) a[i] = As[kk][ty * TM + i];
            #pragma unroll
            for (int j = 0; j < TN; j++) bvv[j] = Bs[kk][tx * TN + j];
            #pragma unroll
            for (int i = 0; i < TM; i++)
                #pragma unroll
                for (int j = 0; j < TN; j++)
                    acc[i][j] = fmaf(a[i], bvv[j], acc[i][j]);
        }
        __syncthreads();
    }

    #pragma unroll
    for (int i = 0; i < TM; i++) {
        const int m = row0 + ty * TM + i;
        #pragma unroll
        for (int j = 0; j < TN; j++) {
            const int n = col0 + tx * TN + j;
            float v = acc[i][j] + (bias ? bias[n] : 0.0f);
            if (EPI == 1) {
                // softplus (stable) -> clip dt -> la -> exp
                float sp  = (v > 20.0f) ? v : log1pf(expf(v));
                float dtv = fminf(fmaxf(sp, 1e-4f), 5.0f);
                float la  = fminf(fmaxf(dtv * extra[n], -18.4206807f), 0.0f);
                v = expf(la);
            }
            C[(size_t)m * ldc + n] = v;
        }
    }
}

// ============================ small kernels ============================

__global__ void acoef_k(const float* __restrict__ A_log, float* __restrict__ Ac)
{
    int d = threadIdx.x;
    Ac[d] = -expf(fminf(fmaxf(A_log[d], -20.0f), 2.0f));
}

// rmsnorm over rows of 64 (one warp per row), in place
__global__ void rmsnorm64_k(float* __restrict__ X, const float* __restrict__ g, int rows)
{
    int w = blockIdx.x * (blockDim.x / 32) + threadIdx.x / 32;
    int lane = threadIdx.x & 31;
    if (w >= rows) return;
    float v0 = X[(size_t)w * 64 + lane];
    float v1 = X[(size_t)w * 64 + lane + 32];
    float ss = v0 * v0 + v1 * v1;
    #pragma unroll
    for (int o = 16; o; o >>= 1) ss += __shfl_xor_sync(0xffffffffu, ss, o);
    float rs = rsqrtf(ss * (1.0f / 64.0f) + 1e-6f);
    X[(size_t)w * 64 + lane]      = v0 * rs * g[lane];
    X[(size_t)w * 64 + lane + 32] = v1 * rs * g[lane + 32];
}

// Intra-chunk recurrence. One block per (b,chunk); thread d carries S[64] in regs.
__global__ void __launch_bounds__(512)
scan_intra_k(const float* __restrict__ xp,     // (M,1024), x_bar at col 0
             const float* __restrict__ Bm,     // (M,64)
             const float* __restrict__ Cm,     // (M,64)
             float* __restrict__ ax,           // in: a=exp(la); out: cumulative decay
             float* __restrict__ Y,            // out: y_intra
             float* __restrict__ cs,           // out: chunk end state (NBLK,64,512)
             float* __restrict__ dtot)         // out: chunk total decay (NBLK,512)
{
    __shared__ float4 Bs[64][16];
    __shared__ float4 Cs[64][16];
    const int blk = blockIdx.x;            // b*64 + chunk; row base = blk*64
    const int d = threadIdx.x;
    const size_t l0 = (size_t)blk * 64;

    for (int t = d; t < 64 * 16; t += 512) {
        int r = t >> 4, c = t & 15;
        Bs[r][c] = ((const float4*)Bm)[(l0 + r) * 16 + c];
        Cs[r][c] = ((const float4*)Cm)[(l0 + r) * 16 + c];
    }
    __syncthreads();

    float S[64];
    #pragma unroll
    for (int n = 0; n < 64; n++) S[n] = 0.0f;
    float dec = 1.0f;

    #pragma unroll 1
    for (int i = 0; i < 64; i++) {
        const size_t m = l0 + i;
        float av = ax[m * 512 + d];
        float xv = xp[m * 1024 + d];
        dec *= av;
        ax[m * 512 + d] = dec;   // store cumulative decay for y_inter
        float y = 0.0f;
        #pragma unroll
        for (int q = 0; q < 16; q++) {
            float4 b4 = Bs[i][q];
            float4 c4 = Cs[i][q];
            S[4 * q + 0] = fmaf(b4.x, xv, av * S[4 * q + 0]); y = fmaf(c4.x, S[4 * q + 0], y);
            S[4 * q + 1] = fmaf(b4.y, xv, av * S[4 * q + 1]); y = fmaf(c4.y, S[4 * q + 1], y);
            S[4 * q + 2] = fmaf(b4.z, xv, av * S[4 * q + 2]); y = fmaf(c4.z, S[4 * q + 2], y);
            S[4 * q + 3] = fmaf(b4.w, xv, av * S[4 * q + 3]); y = fmaf(c4.w, S[4 * q + 3], y);
        }
        Y[m * 512 + d] = y;
    }

    #pragma unroll
    for (int n = 0; n < 64; n++)
        cs[((size_t)blk * 64 + n) * 512 + d] = S[n];
    dtot[(size_t)blk * 512 + d] = dec;
}

// Inter-chunk state scan (sequential over 64 chunks); converts cs -> prev_state in place.
__global__ void state_scan_k(float* __restrict__ cs, const float* __restrict__ dtot)
{
    int idx = blockIdx.x * blockDim.x + threadIdx.x;   // over B*N*D = 131072
    int d = idx & 511;
    int n = (idx >> 9) & 63;
    int b = idx >> 15;
    float s = 0.0f;
    #pragma unroll 1
    for (int ch = 0; ch < 64; ch++) {
        int blk = b * 64 + ch;
        size_t off = ((size_t)blk * 64 + n) * 512 + d;
        float v = cs[off];
        float a = dtot[(size_t)blk * 512 + d];
        cs[off] = s;          // prev_state entering this chunk
        s = fmaf(s, a, v);
    }
}

// y = y_intra + decay * (C @ prev_state) + D_skip * x_bar
__global__ void __launch_bounds__(512)
yinter_k(const float* __restrict__ Cm,
         const float* __restrict__ ps,      // prev states (NBLK,64,512)
         const float* __restrict__ decay,   // (M,512)
         const float* __restrict__ xp,      // x_bar at col 0 of (M,1024)
         const float* __restrict__ Dskip,
         float* __restrict__ Y)
{
    __shared__ float4 Cs[64][16];
    const int blk = blockIdx.x;
    const int d = threadIdx.x;
    const size_t l0 = (size_t)blk * 64;

    for (int t = d; t < 64 * 16; t += 512) {
        int r = t >> 4, c = t & 15;
        Cs[r][c] = ((const float4*)Cm)[(l0 + r) * 16 + c];
    }
    __syncthreads();

    float PS[64];
    #pragma unroll
    for (int n = 0; n < 64; n++)
        PS[n] = ps[((size_t)blk * 64 + n) * 512 + d];
    const float dsk = Dskip[d];

    #pragma unroll 1
    for (int i = 0; i < 64; i++) {
        const size_t m = l0 + i;
        float y = 0.0f;
        #pragma unroll
        for (int q = 0; q < 16; q++) {
            float4 c4 = Cs[i][q];
            y = fmaf(c4.x, PS[4 * q + 0], y);
            y = fmaf(c4.y, PS[4 * q + 1], y);
            y = fmaf(c4.z, PS[4 * q + 2], y);
            y = fmaf(c4.w, PS[4 * q + 3], y);
        }
        float out = Y[m * 512 + d] + decay[m * 512 + d] * y + dsk * xp[m * 1024 + d];
        Y[m * 512 + d] = out;
    }
}

// h = rmsnorm(y, g_outnorm) * silu(z), in place over Y. One block per row.
__global__ void outnorm_k(float* __restrict__ Y, const float* __restrict__ xp,
                          const float* __restrict__ g)
{
    __shared__ float red[256];
    const int m = blockIdx.x;
    const int t = threadIdx.x;
    float v0 = Y[(size_t)m * 512 + t];
    float v1 = Y[(size_t)m * 512 + t + 256];
    float ss = v0 * v0 + v1 * v1;
    red[t] = ss;
    __syncthreads();
    for (int s = 128; s > 0; s >>= 1) {
        if (t < s) red[t] += red[t + s];
        __syncthreads();
    }
    float rs = rsqrtf(red[0] * (1.0f / 512.0f) + 1e-6f);
    float z0 = xp[(size_t)m * 1024 + 512 + t];
    float z1 = xp[(size_t)m * 1024 + 512 + t + 256];
    float s0 = z0 / (1.0f + expf(-z0));
    float s1 = z1 / (1.0f + expf(-z1));
    Y[(size_t)m * 512 + t]       = v0 * rs * g[t] * s0;
    Y[(size_t)m * 512 + t + 256] = v1 * rs * g[t + 256] * s1;
}

// ============================ launch ============================
extern "C" void kernel_launch(void* const* d_in, const int* in_sizes, int n_in,
                              void* d_out, int out_size)
{
    const float* x       = (const float*)d_in[0];
    const float* A_log   = (const float*)d_in[1];
    const float* dt_bias = (const float*)d_in[2];
    const float* D_skip  = (const float*)d_in[3];
    const float* W_xproj = (const float*)d_in[4];
    const float* b_xproj = (const float*)d_in[5];
    const float* W_B     = (const float*)d_in[6];
    const float* W_C     = (const float*)d_in[7];
    const float* W_dt    = (const float*)d_in[8];
    const float* g_Bn    = (const float*)d_in[9];
    const float* g_Cn    = (const float*)d_in[10];
    const float* g_on    = (const float*)d_in[11];
    const float* W_out   = (const float*)d_in[12];
    const float* b_out   = (const float*)d_in[13];
    float* out = (float*)d_out;

    float *p_xp, *p_Bm, *p_Cm, *p_ax, *p_Y, *p_cs, *p_dt, *p_Ac;
    cudaGetSymbolAddress((void**)&p_xp, g_xp);
    cudaGetSymbolAddress((void**)&p_Bm, g_Bm);
    cudaGetSymbolAddress((void**)&p_Cm, g_Cm);
    cudaGetSymbolAddress((void**)&p_ax, g_ax);
    cudaGetSymbolAddress((void**)&p_Y,  g_Yb);
    cudaGetSymbolAddress((void**)&p_cs, g_cs);
    cudaGetSymbolAddress((void**)&p_dt, g_dtot);
    cudaGetSymbolAddress((void**)&p_Ac, g_Ac);

    // A coefficient
    acoef_k<<<1, 512>>>(A_log, p_Ac);

    // xp = x @ W_xproj + b_xproj   (16384 x 1024, K=512)
    sgemm_k<128, 64, 16, 8, 4, 0><<<dim3(1024 / 64, MQ / 128), 256>>>(
        x, 512, W_xproj, 1024, b_xproj, p_xp, 1024, 512, nullptr);

    // B/C projections (16384 x 64, K=512), A = x_bar strided in xp
    sgemm_k<64, 64, 16, 4, 4, 0><<<dim3(1, MQ / 64), 256>>>(
        p_xp, 1024, W_B, 64, nullptr, p_Bm, 64, 512, nullptr);
    sgemm_k<64, 64, 16, 4, 4, 0><<<dim3(1, MQ / 64), 256>>>(
        p_xp, 1024, W_C, 64, nullptr, p_Cm, 64, 512, nullptr);
    rmsnorm64_k<<<MQ / 8, 256>>>(p_Bm, g_Bn, MQ);
    rmsnorm64_k<<<MQ / 8, 256>>>(p_Cm, g_Cn, MQ);

    // a = exp(clip(clip(softplus(x_bar@W_dt + dt_bias),1e-4,5)*A, -18.42, 0))
    sgemm_k<128, 64, 16, 8, 4, 1><<<dim3(512 / 64, MQ / 128), 256>>>(
        p_xp, 1024, W_dt, 512, dt_bias, p_ax, 512, 512, p_Ac);

    // intra-chunk recurrence (also produces cumulative decay + chunk states)
    scan_intra_k<<<NBLK, 512>>>(p_xp, p_Bm, p_Cm, p_ax, p_Y, p_cs, p_dt);

    // inter-chunk state scan (cs -> prev_state, in place)
    state_scan_k<<<(BQ * NQ * DQ) / 256, 256>>>(p_cs, p_dt);

    // y += decay * (C @ prev_state) + D_skip * x_bar
    yinter_k<<<NBLK, 512>>>(p_Cm, p_cs, p_ax, p_xp, D_skip, p_Y);

    // h = rmsnorm(y) * silu(z)
    outnorm_k<<<MQ, 256>>>(p_Y, p_xp, g_on);

    // out = h @ W_out + b_out
    sgemm_k<128, 64, 16, 8, 4, 0><<<dim3(512 / 64, MQ / 128), 256>>>(
        p_Y, 512, W_out, 512, b_out, out, 512, 512, nullptr);
}

// round 4
// speedup vs baseline: 1.8384x; 1.8384x over previous
#include <cuda_runtime.h>
#include <math.h>
#include <stdint.h>

// Problem constants (fixed shapes)
#define BQ 4
#define LQ 4096
#define DQ 512
#define NQ 64
#define MQ (BQ * LQ)        // 16384 rows
#define NBLK 256            // (b,chunk) blocks, chunk=64

// -------- scratch (device globals; no allocation allowed) --------
__device__ float g_xp[(size_t)MQ * 1024];        // xproj out: x_bar [0,512), z [512,1024)
__device__ float g_Bm[(size_t)MQ * 64];          // B proj (rmsnormed)
__device__ float g_Cm[(size_t)MQ * 64];          // C proj (rmsnormed)
__device__ float g_ax[(size_t)MQ * 512];         // a=exp(la); overwritten w/ cumulative decay
__device__ float g_Yb[(size_t)MQ * 512];         // y buffer
__device__ float g_cs[(size_t)NBLK * 64 * 512];  // chunk states -> prev states
__device__ float g_dtot[(size_t)NBLK * 512];     // per-chunk total decay
__device__ float g_Ac[512];                      // A coefficient
// transposed tf32 weights: Wt[n][k], k contiguous (512)
__device__ float g_Wt_xp[1024 * 512];
__device__ float g_Wt_dt[512 * 512];
__device__ float g_Wt_out[512 * 512];
__device__ float g_Wt_bc[128 * 512];             // rows 0..63 = W_B^T, 64..127 = W_C^T

// ============================ helpers ============================
__device__ __forceinline__ uint32_t f2tf32(float x) {
    uint32_t u;
    asm("cvt.rna.tf32.f32 %0, %1;" : "=r"(u) : "f"(x));
    return u;
}
__device__ __forceinline__ void mma_tf32(float* d, const uint32_t* a, const uint32_t* b) {
    asm volatile(
        "mma.sync.aligned.m16n8k8.row.col.f32.tf32.tf32.f32 "
        "{%0,%1,%2,%3}, {%4,%5,%6,%7}, {%8,%9}, {%0,%1,%2,%3};"
        : "+f"(d[0]), "+f"(d[1]), "+f"(d[2]), "+f"(d[3])
        : "r"(a[0]), "r"(a[1]), "r"(a[2]), "r"(a[3]), "r"(b[0]), "r"(b[1]));
}
__device__ __forceinline__ float dt_transform(float v, float Acoef) {
    float sp  = (v > 20.0f) ? v : log1pf(expf(v));
    float dtv = fminf(fmaxf(sp, 1e-4f), 5.0f);
    float la  = fminf(fmaxf(dtv * Acoef, -18.4206807f), 0.0f);
    return expf(la);
}

// ============================ tf32 mma.sync GEMM ============================
// D[128,128] tile per block = A[M,512](lda) * Bt[N,512]^T (Bt row n = col n of W).
// 8 warps (2 M x 4 N), warp tile 64x32, m16n8k8 fragments.
// EPI 0: +bias, store to out0 (ldc)
// EPI 1: dt path: exp(clip(clip(softplus(acc+bias),1e-4,5)*ex0[n], -18.42, 0))
// EPI 2: fused B|C (grid.x==1, BN=128): cols 0..63 -> rmsnorm*ex0 -> out0,
//        cols 64..127 -> rmsnorm*ex1 -> out1 (both ld 64)
template <int EPI>
__global__ void __launch_bounds__(256)
mma_gemm_k(const float* __restrict__ A, int lda,
           const float* __restrict__ Bt,
           const float* __restrict__ bias,
           float* __restrict__ out0, float* __restrict__ out1, int ldc,
           const float* __restrict__ ex0, const float* __restrict__ ex1)
{
    __shared__ float As[128 * 36];   // [m][k], pad 4
    __shared__ float Bs[128 * 36];   // [n][k], pad 4
    __shared__ float ssred[256];     // EPI2: [half][row]

    uint32_t* Asu = (uint32_t*)As;
    uint32_t* Bsu = (uint32_t*)Bs;

    const int tid = threadIdx.x;
    const int wid = tid >> 5;
    const int lane = tid & 31;
    const int g = lane >> 2;        // groupID
    const int tig = lane & 3;       // thread-in-group
    const int warp_m = wid >> 2;    // 0..1
    const int warp_n = wid & 3;     // 0..3
    const int row0 = blockIdx.y * 128;
    const int col0 = blockIdx.x * 128;

    if (EPI == 2) { ssred[tid] = 0.0f; }

    const int ld_m = tid >> 3;      // 0..31 step? -> idx covers below
    const int ld_k4 = tid & 7;

    float4 ra[4], rb[4];
    // prefetch chunk 0
    #pragma unroll
    for (int j = 0; j < 4; j++) {
        const int m = (tid + 256 * j) >> 3;
        const int k4 = (tid + 256 * j) & 7;
        ra[j] = *(const float4*)&A[(size_t)(row0 + m) * lda + k4 * 4];
        rb[j] = *(const float4*)&Bt[(size_t)(col0 + m) * 512 + k4 * 4];
    }

    float acc[4][4][4] = {};

    #pragma unroll 1
    for (int c = 0; c < 16; c++) {
        // store staged chunk to smem (cvt A to tf32; Bt already tf32)
        #pragma unroll
        for (int j = 0; j < 4; j++) {
            const int m = (tid + 256 * j) >> 3;
            const int k4 = (tid + 256 * j) & 7;
            uint4 ua = make_uint4(f2tf32(ra[j].x), f2tf32(ra[j].y),
                                  f2tf32(ra[j].z), f2tf32(ra[j].w));
            *(uint4*)&Asu[m * 36 + k4 * 4] = ua;
            *(float4*)&Bs[m * 36 + k4 * 4] = rb[j];
        }
        __syncthreads();
        if (c < 15) {
            const int k0 = (c + 1) * 32;
            #pragma unroll
            for (int j = 0; j < 4; j++) {
                const int m = (tid + 256 * j) >> 3;
                const int k4 = (tid + 256 * j) & 7;
                ra[j] = *(const float4*)&A[(size_t)(row0 + m) * lda + k0 + k4 * 4];
                rb[j] = *(const float4*)&Bt[(size_t)(col0 + m) * 512 + k0 + k4 * 4];
            }
        }
        // compute 4 k8 steps
        #pragma unroll
        for (int kk = 0; kk < 4; kk++) {
            const int k = kk * 8;
            uint32_t af[4][4];
            #pragma unroll
            for (int mi = 0; mi < 4; mi++) {
                const int mr = warp_m * 64 + mi * 16 + g;
                af[mi][0] = Asu[mr * 36 + k + tig];
                af[mi][1] = Asu[(mr + 8) * 36 + k + tig];
                af[mi][2] = Asu[mr * 36 + k + tig + 4];
                af[mi][3] = Asu[(mr + 8) * 36 + k + tig + 4];
            }
            #pragma unroll
            for (int ni = 0; ni < 4; ni++) {
                uint32_t bf[2];
                const int nr = warp_n * 32 + ni * 8 + g;
                bf[0] = Bsu[nr * 36 + k + tig];
                bf[1] = Bsu[nr * 36 + k + tig + 4];
                #pragma unroll
                for (int mi = 0; mi < 4; mi++)
                    mma_tf32(acc[mi][ni], af[mi], bf);
            }
        }
        __syncthreads();
    }

    // ---------------- epilogue ----------------
    if (EPI == 2) {
        const int half = warp_n >> 1;                 // 0 = B, 1 = C
        // per-row partial sum of squares
        #pragma unroll
        for (int mi = 0; mi < 4; mi++) {
            float s0 = 0.0f, s1 = 0.0f;
            #pragma unroll
            for (int ni = 0; ni < 4; ni++) {
                s0 += acc[mi][ni][0] * acc[mi][ni][0] + acc[mi][ni][1] * acc[mi][ni][1];
                s1 += acc[mi][ni][2] * acc[mi][ni][2] + acc[mi][ni][3] * acc[mi][ni][3];
            }
            s0 += __shfl_xor_sync(0xffffffffu, s0, 1);
            s0 += __shfl_xor_sync(0xffffffffu, s0, 2);
            s1 += __shfl_xor_sync(0xffffffffu, s1, 1);
            s1 += __shfl_xor_sync(0xffffffffu, s1, 2);
            if (tig == 0) {
                const int r = warp_m * 64 + mi * 16 + g;
                atomicAdd(&ssred[half * 128 + r], s0);
                atomicAdd(&ssred[half * 128 + r + 8], s1);
            }
        }
        __syncthreads();
        const float* gam = half ? ex1 : ex0;
        float* outp = half ? out1 : out0;
        #pragma unroll
        for (int mi = 0; mi < 4; mi++) {
            const int r = warp_m * 64 + mi * 16 + g;
            const float rs0 = rsqrtf(ssred[half * 128 + r] * (1.0f / 64.0f) + 1e-6f);
            const float rs1 = rsqrtf(ssred[half * 128 + r + 8] * (1.0f / 64.0f) + 1e-6f);
            #pragma unroll
            for (int ni = 0; ni < 4; ni++) {
                const int nl = (warp_n - half * 2) * 32 + ni * 8 + 2 * tig;  // 0..63
                const float g0 = gam[nl], g1 = gam[nl + 1];
                float2 v0 = make_float2(acc[mi][ni][0] * rs0 * g0,
                                        acc[mi][ni][1] * rs0 * g1);
                float2 v1 = make_float2(acc[mi][ni][2] * rs1 * g0,
                                        acc[mi][ni][3] * rs1 * g1);
                *(float2*)&outp[(size_t)(row0 + r) * 64 + nl] = v0;
                *(float2*)&outp[(size_t)(row0 + r + 8) * 64 + nl] = v1;
            }
        }
    } else {
        #pragma unroll
        for (int mi = 0; mi < 4; mi++) {
            const int m = row0 + warp_m * 64 + mi * 16 + g;
            #pragma unroll
            for (int ni = 0; ni < 4; ni++) {
                const int n = col0 + warp_n * 32 + ni * 8 + 2 * tig;
                float d0 = acc[mi][ni][0], d1 = acc[mi][ni][1];
                float d2 = acc[mi][ni][2], d3 = acc[mi][ni][3];
                if (bias) {
                    const float b0 = bias[n], b1 = bias[n + 1];
                    d0 += b0; d1 += b1; d2 += b0; d3 += b1;
                }
                if (EPI == 1) {
                    const float a0 = ex0[n], a1 = ex0[n + 1];
                    d0 = dt_transform(d0, a0); d1 = dt_transform(d1, a1);
                    d2 = dt_transform(d2, a0); d3 = dt_transform(d3, a1);
                }
                *(float2*)&out0[(size_t)m * ldc + n] = make_float2(d0, d1);
                *(float2*)&out0[(size_t)(m + 8) * ldc + n] = make_float2(d2, d3);
            }
        }
    }
}

// ============================ small kernels ============================

__global__ void acoef_k(const float* __restrict__ A_log, float* __restrict__ Ac)
{
    int d = threadIdx.x;
    Ac[d] = -expf(fminf(fmaxf(A_log[d], -20.0f), 2.0f));
}

// Wt[n][k] = tf32(W[k][n]); K, N multiples of 32
__global__ void transpose_cvt_k(const float* __restrict__ W, float* __restrict__ Wt,
                                int K, int N)
{
    __shared__ float tile[32][33];
    const int k0 = blockIdx.y * 32, n0 = blockIdx.x * 32;
    const int tx = threadIdx.x, ty = threadIdx.y;
    for (int i = ty; i < 32; i += 8)
        tile[i][tx] = W[(size_t)(k0 + i) * N + n0 + tx];
    __syncthreads();
    for (int i = ty; i < 32; i += 8)
        Wt[(size_t)(n0 + i) * K + k0 + tx] = __uint_as_float(f2tf32(tile[tx][i]));
}

// Intra-chunk recurrence. One block per (b,chunk); thread d carries S[64] in regs.
__global__ void __launch_bounds__(512)
scan_intra_k(const float* __restrict__ xp, const float* __restrict__ Bm,
             const float* __restrict__ Cm, float* __restrict__ ax,
             float* __restrict__ Y, float* __restrict__ cs, float* __restrict__ dtot)
{
    __shared__ float4 Bs[64][16];
    __shared__ float4 Cs[64][16];
    const int blk = blockIdx.x;
    const int d = threadIdx.x;
    const size_t l0 = (size_t)blk * 64;

    for (int t = d; t < 64 * 16; t += 512) {
        int r = t >> 4, c = t & 15;
        Bs[r][c] = ((const float4*)Bm)[(l0 + r) * 16 + c];
        Cs[r][c] = ((const float4*)Cm)[(l0 + r) * 16 + c];
    }
    __syncthreads();

    float S[64];
    #pragma unroll
    for (int n = 0; n < 64; n++) S[n] = 0.0f;
    float dec = 1.0f;

    #pragma unroll 1
    for (int i = 0; i < 64; i++) {
        const size_t m = l0 + i;
        float av = ax[m * 512 + d];
        float xv = xp[m * 1024 + d];
        dec *= av;
        ax[m * 512 + d] = dec;
        float y = 0.0f;
        #pragma unroll
        for (int q = 0; q < 16; q++) {
            float4 b4 = Bs[i][q];
            float4 c4 = Cs[i][q];
            S[4*q+0] = fmaf(b4.x, xv, av * S[4*q+0]); y = fmaf(c4.x, S[4*q+0], y);
            S[4*q+1] = fmaf(b4.y, xv, av * S[4*q+1]); y = fmaf(c4.y, S[4*q+1], y);
            S[4*q+2] = fmaf(b4.z, xv, av * S[4*q+2]); y = fmaf(c4.z, S[4*q+2], y);
            S[4*q+3] = fmaf(b4.w, xv, av * S[4*q+3]); y = fmaf(c4.w, S[4*q+3], y);
        }
        Y[m * 512 + d] = y;
    }

    #pragma unroll
    for (int n = 0; n < 64; n++)
        cs[((size_t)blk * 64 + n) * 512 + d] = S[n];
    dtot[(size_t)blk * 512 + d] = dec;
}

// Inter-chunk state scan (sequential over 64 chunks); cs -> prev_state in place.
__global__ void state_scan_k(float* __restrict__ cs, const float* __restrict__ dtot)
{
    int idx = blockIdx.x * blockDim.x + threadIdx.x;
    int d = idx & 511;
    int n = (idx >> 9) & 63;
    int b = idx >> 15;
    float s = 0.0f;
    #pragma unroll 1
    for (int ch = 0; ch < 64; ch++) {
        int blk = b * 64 + ch;
        size_t off = ((size_t)blk * 64 + n) * 512 + d;
        float v = cs[off];
        float a = dtot[(size_t)blk * 512 + d];
        cs[off] = s;
        s = fmaf(s, a, v);
    }
}

// y = y_intra + decay * (C @ prev_state) + D_skip * x_bar
__global__ void __launch_bounds__(512)
yinter_k(const float* __restrict__ Cm, const float* __restrict__ ps,
         const float* __restrict__ decay, const float* __restrict__ xp,
         const float* __restrict__ Dskip, float* __restrict__ Y)
{
    __shared__ float4 Cs[64][16];
    const int blk = blockIdx.x;
    const int d = threadIdx.x;
    const size_t l0 = (size_t)blk * 64;

    for (int t = d; t < 64 * 16; t += 512) {
        int r = t >> 4, c = t & 15;
        Cs[r][c] = ((const float4*)Cm)[(l0 + r) * 16 + c];
    }
    __syncthreads();

    float PS[64];
    #pragma unroll
    for (int n = 0; n < 64; n++)
        PS[n] = ps[((size_t)blk * 64 + n) * 512 + d];
    const float dsk = Dskip[d];

    #pragma unroll 1
    for (int i = 0; i < 64; i++) {
        const size_t m = l0 + i;
        float y = 0.0f;
        #pragma unroll
        for (int q = 0; q < 16; q++) {
            float4 c4 = Cs[i][q];
            y = fmaf(c4.x, PS[4*q+0], y);
            y = fmaf(c4.y, PS[4*q+1], y);
            y = fmaf(c4.z, PS[4*q+2], y);
            y = fmaf(c4.w, PS[4*q+3], y);
        }
        Y[m * 512 + d] = Y[m * 512 + d] + decay[m * 512 + d] * y + dsk * xp[m * 1024 + d];
    }
}

// h = rmsnorm(y, g_outnorm) * silu(z), in place over Y.
__global__ void outnorm_k(float* __restrict__ Y, const float* __restrict__ xp,
                          const float* __restrict__ g)
{
    __shared__ float red[256];
    const int m = blockIdx.x;
    const int t = threadIdx.x;
    float v0 = Y[(size_t)m * 512 + t];
    float v1 = Y[(size_t)m * 512 + t + 256];
    red[t] = v0 * v0 + v1 * v1;
    __syncthreads();
    for (int s = 128; s > 0; s >>= 1) {
        if (t < s) red[t] += red[t + s];
        __syncthreads();
    }
    float rs = rsqrtf(red[0] * (1.0f / 512.0f) + 1e-6f);
    float z0 = xp[(size_t)m * 1024 + 512 + t];
    float z1 = xp[(size_t)m * 1024 + 512 + t + 256];
    float s0 = z0 / (1.0f + expf(-z0));
    float s1 = z1 / (1.0f + expf(-z1));
    Y[(size_t)m * 512 + t]       = v0 * rs * g[t] * s0;
    Y[(size_t)m * 512 + t + 256] = v1 * rs * g[t + 256] * s1;
}

// ============================ launch ============================
extern "C" void kernel_launch(void* const* d_in, const int* in_sizes, int n_in,
                              void* d_out, int out_size)
{
    const float* x       = (const float*)d_in[0];
    const float* A_log   = (const float*)d_in[1];
    const float* dt_bias = (const float*)d_in[2];
    const float* D_skip  = (const float*)d_in[3];
    const float* W_xproj = (const float*)d_in[4];
    const float* b_xproj = (const float*)d_in[5];
    const float* W_B     = (const float*)d_in[6];
    const float* W_C     = (const float*)d_in[7];
    const float* W_dt    = (const float*)d_in[8];
    const float* g_Bn    = (const float*)d_in[9];
    const float* g_Cn    = (const float*)d_in[10];
    const float* g_on    = (const float*)d_in[11];
    const float* W_out   = (const float*)d_in[12];
    const float* b_out   = (const float*)d_in[13];
    float* out = (float*)d_out;

    float *p_xp, *p_Bm, *p_Cm, *p_ax, *p_Y, *p_cs, *p_dt, *p_Ac;
    float *p_Wxp, *p_Wdt, *p_Wout, *p_Wbc;
    cudaGetSymbolAddress((void**)&p_xp, g_xp);
    cudaGetSymbolAddress((void**)&p_Bm, g_Bm);
    cudaGetSymbolAddress((void**)&p_Cm, g_Cm);
    cudaGetSymbolAddress((void**)&p_ax, g_ax);
    cudaGetSymbolAddress((void**)&p_Y,  g_Yb);
    cudaGetSymbolAddress((void**)&p_cs, g_cs);
    cudaGetSymbolAddress((void**)&p_dt, g_dtot);
    cudaGetSymbolAddress((void**)&p_Ac, g_Ac);
    cudaGetSymbolAddress((void**)&p_Wxp,  g_Wt_xp);
    cudaGetSymbolAddress((void**)&p_Wdt,  g_Wt_dt);
    cudaGetSymbolAddress((void**)&p_Wout, g_Wt_out);
    cudaGetSymbolAddress((void**)&p_Wbc,  g_Wt_bc);

    // weight prep (tiny)
    acoef_k<<<1, 512>>>(A_log, p_Ac);
    transpose_cvt_k<<<dim3(1024/32, 512/32), dim3(32, 8)>>>(W_xproj, p_Wxp, 512, 1024);
    transpose_cvt_k<<<dim3(512/32,  512/32), dim3(32, 8)>>>(W_dt,    p_Wdt, 512, 512);
    transpose_cvt_k<<<dim3(512/32,  512/32), dim3(32, 8)>>>(W_out,   p_Wout, 512, 512);
    transpose_cvt_k<<<dim3(64/32,   512/32), dim3(32, 8)>>>(W_B,  p_Wbc,            512, 64);
    transpose_cvt_k<<<dim3(64/32,   512/32), dim3(32, 8)>>>(W_C,  p_Wbc + 64 * 512, 512, 64);

    // xp = x @ W_xproj + b_xproj
    mma_gemm_k<0><<<dim3(8, 128), 256>>>(
        x, 512, p_Wxp, b_xproj, p_xp, nullptr, 1024, nullptr, nullptr);

    // fused B|C projection + rmsnorm
    mma_gemm_k<2><<<dim3(1, 128), 256>>>(
        p_xp, 1024, p_Wbc, nullptr, p_Bm, p_Cm, 64, g_Bn, g_Cn);

    // a = exp(clip(clip(softplus(x_bar@W_dt + dt_bias),1e-4,5)*A, -18.42, 0))
    mma_gemm_k<1><<<dim3(4, 128), 256>>>(
        p_xp, 1024, p_Wdt, dt_bias, p_ax, nullptr, 512, p_Ac, nullptr);

    // intra-chunk recurrence
    scan_intra_k<<<NBLK, 512>>>(p_xp, p_Bm, p_Cm, p_ax, p_Y, p_cs, p_dt);
    // inter-chunk state scan
    state_scan_k<<<(BQ * NQ * DQ) / 256, 256>>>(p_cs, p_dt);
    // y += decay * (C @ prev_state) + D_skip * x_bar
    yinter_k<<<NBLK, 512>>>(p_Cm, p_cs, p_ax, p_xp, D_skip, p_Y);
    // h = rmsnorm(y) * silu(z)
    outnorm_k<<<MQ, 256>>>(p_Y, p_xp, g_on);

    // out = h @ W_out + b_out
    mma_gemm_k<0><<<dim3(4, 128), 256>>>(
        p_Y, 512, p_Wout, b_out, out, nullptr, 512, nullptr, nullptr);
}

// round 6
// speedup vs baseline: 2.2208x; 1.2080x over previous
#include <cuda_runtime.h>
#include <math.h>
#include <stdint.h>

// Problem constants (fixed shapes)
#define BQ 4
#define LQ 4096
#define DQ 512
#define NQ 64
#define MQ (BQ * LQ)        // 16384 rows
#define NBLK 256            // (b,chunk) blocks, chunk=64

typedef unsigned long long ull;

// -------- scratch (device globals; no allocation allowed) --------
__device__ float g_xp[(size_t)MQ * 1024];        // xproj out: x_bar [0,512), z [512,1024)
__device__ float g_xt[(size_t)MQ * 512];         // tf32-rounded x
__device__ float g_xbt[(size_t)MQ * 512];        // tf32-rounded x_bar
__device__ float g_Bm[(size_t)MQ * 64];          // B proj (rmsnormed)
__device__ float g_Cm[(size_t)MQ * 64];          // C proj (rmsnormed)
__device__ float g_ax[(size_t)MQ * 512];         // a=exp(la); overwritten w/ cumulative decay
__device__ float g_Yb[(size_t)MQ * 512];         // y buffer (h stored tf32-rounded)
__device__ float g_cs[(size_t)NBLK * 64 * 512];  // chunk states -> prev states
__device__ float g_dtot[(size_t)NBLK * 512];     // per-chunk total decay
__device__ float g_Ac[512];                      // A coefficient
// transposed tf32 weights: Wt[n][k], k contiguous (512)
__device__ float g_Wt_xp[1024 * 512];
__device__ float g_Wt_dt[512 * 512];
__device__ float g_Wt_out[512 * 512];
__device__ float g_Wt_bc[128 * 512];             // rows 0..63 = W_B^T, 64..127 = W_C^T

// ============================ helpers ============================
__device__ __forceinline__ uint32_t f2tf32(float x) {
    uint32_t u;
    asm("cvt.rna.tf32.f32 %0, %1;" : "=r"(u) : "f"(x));
    return u;
}
__device__ __forceinline__ void mma_tf32(float* d, const uint32_t* a, const uint32_t* b) {
    asm volatile(
        "mma.sync.aligned.m16n8k8.row.col.f32.tf32.tf32.f32 "
        "{%0,%1,%2,%3}, {%4,%5,%6,%7}, {%8,%9}, {%0,%1,%2,%3};"
        : "+f"(d[0]), "+f"(d[1]), "+f"(d[2]), "+f"(d[3])
        : "r"(a[0]), "r"(a[1]), "r"(a[2]), "r"(a[3]), "r"(b[0]), "r"(b[1]));
}
__device__ __forceinline__ float dt_transform(float v, float Acoef) {
    float sp  = (v > 20.0f) ? v : log1pf(expf(v));
    float dtv = fminf(fmaxf(sp, 1e-4f), 5.0f);
    float la  = fminf(fmaxf(dtv * Acoef, -18.4206807f), 0.0f);
    return expf(la);
}
__device__ __forceinline__ void cpasync16(uint32_t saddr, const void* g) {
    asm volatile("cp.async.cg.shared.global [%0], [%1], 16;" :: "r"(saddr), "l"(g));
}
#define CP_COMMIT() asm volatile("cp.async.commit_group;" ::: "memory")
#define CP_WAIT1()  asm volatile("cp.async.wait_group 1;" ::: "memory")
#define CP_WAIT0()  asm volatile("cp.async.wait_group 0;" ::: "memory")

__device__ __forceinline__ ull pack2(float lo, float hi) {
    ull r; asm("mov.b64 %0, {%1, %2};" : "=l"(r) : "f"(lo), "f"(hi)); return r;
}
__device__ __forceinline__ void unpack2(ull v, float& lo, float& hi) {
    asm("mov.b64 {%0, %1}, %2;" : "=f"(lo), "=f"(hi) : "l"(v));
}
#define FMA2_ACC(d, a, b) \
    asm("fma.rn.f32x2 %0, %1, %2, %0;" : "+l"(d) : "l"(a), "l"(b))
#define MUL2(d, a, b) \
    asm("mul.rn.f32x2 %0, %1, %2;" : "=l"(d) : "l"(a), "l"(b))

// ============================ tf32 mma.sync GEMM (cp.async) ============================
// D[128,128] tile per block = A[M,512](lda, pre-rounded tf32) * Bt[N,512]^T (tf32).
// 8 warps (2 M x 4 N), warp tile 64x32, m16n8k8 fragments.
// EPI 0: +bias -> out0 (ldc)
// EPI 1: dt path: exp(clip(clip(softplus(acc+bias),1e-4,5)*ex0[n], -18.42, 0)) -> out0
// EPI 2: fused B|C (grid.x==1): cols 0..63 -> rmsnorm*ex0 -> out0 (ld 64),
//        cols 64..127 -> rmsnorm*ex1 -> out1 (ld 64)
// EPI 3: xproj: +bias -> out0 (ldc=1024); cols<512 also store tf32-rounded -> out1 (ld 512)
#define STG_F (128 * 36)
template <int EPI>
__global__ void __launch_bounds__(256, 2)
mma_gemm_k(const float* __restrict__ A, int lda,
           const float* __restrict__ Bt,
           const float* __restrict__ bias,
           float* __restrict__ out0, float* __restrict__ out1, int ldc,
           const float* __restrict__ ex0, const float* __restrict__ ex1)
{
    extern __shared__ float sm[];
    __shared__ float ssred[256];

    const int tid = threadIdx.x;
    const int wid = tid >> 5;
    const int lane = tid & 31;
    const int g = lane >> 2;
    const int tig = lane & 3;
    const int warp_m = wid >> 2;    // 0..1
    const int warp_n = wid & 3;     // 0..3
    const int row0 = blockIdx.y * 128;
    const int col0 = blockIdx.x * 128;

    if (EPI == 2) ssred[tid] = 0.0f;

    float* Asm = sm;                 // 2 stages x 128x36
    float* Bsm = sm + 2 * STG_F;
    const uint32_t asm_u = (uint32_t)__cvta_generic_to_shared(Asm);
    const uint32_t bsm_u = (uint32_t)__cvta_generic_to_shared(Bsm);

    const int ldm = tid >> 3;        // base row this thread loads (plus 32*j)
    const int ldk4 = tid & 7;

    // issue stage s for k-chunk k0
    auto issue = [&](int s, int k0) {
        #pragma unroll
        for (int j = 0; j < 4; j++) {
            const int m = ldm + 32 * j;
            const uint32_t off = (uint32_t)((s * STG_F + m * 36 + ldk4 * 4) * 4);
            cpasync16(asm_u + off, &A[(size_t)(row0 + m) * lda + k0 + ldk4 * 4]);
            cpasync16(bsm_u + off, &Bt[(size_t)(col0 + m) * 512 + k0 + ldk4 * 4]);
        }
        CP_COMMIT();
    };

    issue(0, 0);
    issue(1, 32);

    float acc[4][4][4] = {};

    #pragma unroll 1
    for (int c = 0; c < 16; c++) {
        const int s = c & 1;
        if (c < 15) { CP_WAIT1(); } else { CP_WAIT0(); }  // last iter: newest group must land
        __syncthreads();
        const uint32_t* AsU = (const uint32_t*)(Asm + s * STG_F);
        const uint32_t* BsU = (const uint32_t*)(Bsm + s * STG_F);
        #pragma unroll
        for (int kk = 0; kk < 4; kk++) {
            const int k = kk * 8;
            uint32_t af[4][4];
            #pragma unroll
            for (int mi = 0; mi < 4; mi++) {
                const int mr = warp_m * 64 + mi * 16 + g;
                af[mi][0] = AsU[mr * 36 + k + tig];
                af[mi][1] = AsU[(mr + 8) * 36 + k + tig];
                af[mi][2] = AsU[mr * 36 + k + tig + 4];
                af[mi][3] = AsU[(mr + 8) * 36 + k + tig + 4];
            }
            #pragma unroll
            for (int ni = 0; ni < 4; ni++) {
                uint32_t bf[2];
                const int nr = warp_n * 32 + ni * 8 + g;
                bf[0] = BsU[nr * 36 + k + tig];
                bf[1] = BsU[nr * 36 + k + tig + 4];
                #pragma unroll
                for (int mi = 0; mi < 4; mi++)
                    mma_tf32(acc[mi][ni], af[mi], bf);
            }
        }
        __syncthreads();
        if (c + 2 < 16) issue(s, (c + 2) * 32);
    }

    // ---------------- epilogue ----------------
    if (EPI == 2) {
        const int half = warp_n >> 1;                 // 0 = B, 1 = C
        #pragma unroll
        for (int mi = 0; mi < 4; mi++) {
            float s0 = 0.0f, s1 = 0.0f;
            #pragma unroll
            for (int ni = 0; ni < 4; ni++) {
                s0 += acc[mi][ni][0] * acc[mi][ni][0] + acc[mi][ni][1] * acc[mi][ni][1];
                s1 += acc[mi][ni][2] * acc[mi][ni][2] + acc[mi][ni][3] * acc[mi][ni][3];
            }
            s0 += __shfl_xor_sync(0xffffffffu, s0, 1);
            s0 += __shfl_xor_sync(0xffffffffu, s0, 2);
            s1 += __shfl_xor_sync(0xffffffffu, s1, 1);
            s1 += __shfl_xor_sync(0xffffffffu, s1, 2);
            if (tig == 0) {
                const int r = warp_m * 64 + mi * 16 + g;
                atomicAdd(&ssred[half * 128 + r], s0);
                atomicAdd(&ssred[half * 128 + r + 8], s1);
            }
        }
        __syncthreads();
        const float* gam = half ? ex1 : ex0;
        float* outp = half ? out1 : out0;
        #pragma unroll
        for (int mi = 0; mi < 4; mi++) {
            const int r = warp_m * 64 + mi * 16 + g;
            const float rs0 = rsqrtf(ssred[half * 128 + r] * (1.0f / 64.0f) + 1e-6f);
            const float rs1 = rsqrtf(ssred[half * 128 + r + 8] * (1.0f / 64.0f) + 1e-6f);
            #pragma unroll
            for (int ni = 0; ni < 4; ni++) {
                const int nl = (warp_n - half * 2) * 32 + ni * 8 + 2 * tig;  // 0..63
                const float g0 = gam[nl], g1 = gam[nl + 1];
                *(float2*)&outp[(size_t)(row0 + r) * 64 + nl] =
                    make_float2(acc[mi][ni][0] * rs0 * g0, acc[mi][ni][1] * rs0 * g1);
                *(float2*)&outp[(size_t)(row0 + r + 8) * 64 + nl] =
                    make_float2(acc[mi][ni][2] * rs1 * g0, acc[mi][ni][3] * rs1 * g1);
            }
        }
    } else {
        #pragma unroll
        for (int mi = 0; mi < 4; mi++) {
            const int m = row0 + warp_m * 64 + mi * 16 + g;
            #pragma unroll
            for (int ni = 0; ni < 4; ni++) {
                const int n = col0 + warp_n * 32 + ni * 8 + 2 * tig;
                float d0 = acc[mi][ni][0], d1 = acc[mi][ni][1];
                float d2 = acc[mi][ni][2], d3 = acc[mi][ni][3];
                if (bias) {
                    const float b0 = bias[n], b1 = bias[n + 1];
                    d0 += b0; d1 += b1; d2 += b0; d3 += b1;
                }
                if (EPI == 1) {
                    const float a0 = ex0[n], a1 = ex0[n + 1];
                    d0 = dt_transform(d0, a0); d1 = dt_transform(d1, a1);
                    d2 = dt_transform(d2, a0); d3 = dt_transform(d3, a1);
                }
                *(float2*)&out0[(size_t)m * ldc + n] = make_float2(d0, d1);
                *(float2*)&out0[(size_t)(m + 8) * ldc + n] = make_float2(d2, d3);
                if (EPI == 3 && n < 512) {
                    *(float2*)&out1[(size_t)m * 512 + n] = make_float2(
                        __uint_as_float(f2tf32(d0)), __uint_as_float(f2tf32(d1)));
                    *(float2*)&out1[(size_t)(m + 8) * 512 + n] = make_float2(
                        __uint_as_float(f2tf32(d2)), __uint_as_float(f2tf32(d3)));
                }
            }
        }
    }
}

// ============================ prep kernels ============================

__global__ void acoef_k(const float* __restrict__ A_log, float* __restrict__ Ac)
{
    int d = threadIdx.x;
    Ac[d] = -expf(fminf(fmaxf(A_log[d], -20.0f), 2.0f));
}

// Merged: [0,8192): round x -> xt (float4/thread). [8192,9280): weight transposes+cvt.
__global__ void __launch_bounds__(256)
prep_k(const float* __restrict__ x,
       const float* __restrict__ Wxp, const float* __restrict__ Wdt,
       const float* __restrict__ Wout, const float* __restrict__ WB,
       const float* __restrict__ WC,
       float* __restrict__ xt, float* __restrict__ Twxp, float* __restrict__ Twdt,
       float* __restrict__ Twout, float* __restrict__ Twbc)
{
    int bid = blockIdx.x;
    if (bid < 8192) {
        const int i = bid * 256 + threadIdx.x;
        float4 v = ((const float4*)x)[i];
        ((uint4*)xt)[i] = make_uint4(f2tf32(v.x), f2tf32(v.y), f2tf32(v.z), f2tf32(v.w));
        return;
    }
    bid -= 8192;
    const float* W; float* Wt; int N, lb;
    if (bid < 512)       { W = Wxp;  Wt = Twxp;            N = 1024; lb = bid; }
    else if (bid < 768)  { W = Wdt;  Wt = Twdt;            N = 512;  lb = bid - 512; }
    else if (bid < 1024) { W = Wout; Wt = Twout;           N = 512;  lb = bid - 768; }
    else if (bid < 1056) { W = WB;   Wt = Twbc;            N = 64;   lb = bid - 1024; }
    else                 { W = WC;   Wt = Twbc + 64 * 512; N = 64;   lb = bid - 1056; }
    const int tiles_n = N / 32;
    const int n0 = (lb % tiles_n) * 32;
    const int k0 = (lb / tiles_n) * 32;
    __shared__ float tile[32][33];
    const int tx = threadIdx.x & 31, ty = threadIdx.x >> 5;
    for (int i = ty; i < 32; i += 8)
        tile[i][tx] = W[(size_t)(k0 + i) * N + n0 + tx];
    __syncthreads();
    for (int i = ty; i < 32; i += 8)
        Wt[(size_t)(n0 + i) * 512 + k0 + tx] = __uint_as_float(f2tf32(tile[tx][i]));
}

// ============================ scan kernels ============================

// Intra-chunk recurrence (f32x2). One block per (b,chunk); thread d carries S[64].
__global__ void __launch_bounds__(512)
scan_intra_k(const float* __restrict__ xp, const float* __restrict__ Bm,
             const float* __restrict__ Cm, float* __restrict__ ax,
             float* __restrict__ Y, float* __restrict__ cs, float* __restrict__ dtot)
{
    __shared__ float4 Bs[64][16];
    __shared__ float4 Cs[64][16];
    const int blk = blockIdx.x;
    const int d = threadIdx.x;
    const size_t l0 = (size_t)blk * 64;

    for (int t = d; t < 64 * 16; t += 512) {
        int r = t >> 4, c = t & 15;
        Bs[r][c] = ((const float4*)Bm)[(l0 + r) * 16 + c];
        Cs[r][c] = ((const float4*)Cm)[(l0 + r) * 16 + c];
    }
    __syncthreads();

    ull S2[32];
    #pragma unroll
    for (int q = 0; q < 32; q++) S2[q] = 0ull;
    float dec = 1.0f;

    #pragma unroll 1
    for (int i = 0; i < 64; i++) {
        const size_t m = l0 + i;
        const float av = ax[m * 512 + d];
        const float xv = xp[m * 1024 + d];
        dec *= av;
        ax[m * 512 + d] = dec;
        const ull av2 = pack2(av, av);
        const ull xv2 = pack2(xv, xv);
        const ull* Bp = (const ull*)&Bs[i][0];
        const ull* Cp = (const ull*)&Cs[i][0];
        ull y2 = 0ull;
        #pragma unroll
        for (int q = 0; q < 32; q++) {
            ull b2 = Bp[q];
            ull c2 = Cp[q];
            ull bx; MUL2(bx, b2, xv2);
            FMA2_ACC(bx, av2, S2[q]);   // bx = av*S + b*x
            S2[q] = bx;
            FMA2_ACC(y2, c2, S2[q]);
        }
        float ylo, yhi; unpack2(y2, ylo, yhi);
        Y[m * 512 + d] = ylo + yhi;
    }

    #pragma unroll
    for (int q = 0; q < 32; q++) {
        float slo, shi; unpack2(S2[q], slo, shi);
        cs[((size_t)blk * 64 + 2 * q) * 512 + d] = slo;
        cs[((size_t)blk * 64 + 2 * q + 1) * 512 + d] = shi;
    }
    dtot[(size_t)blk * 512 + d] = dec;
}

// Inter-chunk state scan, float4 over d; cs -> prev_state in place.
__global__ void state_scan_k(float* __restrict__ cs, const float* __restrict__ dtot)
{
    const int idx = blockIdx.x * blockDim.x + threadIdx.x;   // B*N*128 = 32768
    const int d4 = idx & 127;
    const int n = (idx >> 7) & 63;
    const int b = idx >> 13;
    float4* cs4 = (float4*)cs;
    const float4* dt4 = (const float4*)dtot;
    float4 s = make_float4(0.f, 0.f, 0.f, 0.f);
    #pragma unroll 1
    for (int ch = 0; ch < 64; ch++) {
        const int blk = b * 64 + ch;
        const size_t off = ((size_t)blk * 64 + n) * 128 + d4;
        float4 v = cs4[off];
        float4 a = dt4[(size_t)blk * 128 + d4];
        cs4[off] = s;
        s.x = fmaf(s.x, a.x, v.x);
        s.y = fmaf(s.y, a.y, v.y);
        s.z = fmaf(s.z, a.z, v.z);
        s.w = fmaf(s.w, a.w, v.w);
    }
}

// y = y_intra + decay * (C @ prev_state) + D_skip * x_bar   (f32x2)
__global__ void __launch_bounds__(512)
yinter_k(const float* __restrict__ Cm, const float* __restrict__ ps,
         const float* __restrict__ decay, const float* __restrict__ xp,
         const float* __restrict__ Dskip, float* __restrict__ Y)
{
    __shared__ float4 Cs[64][16];
    const int blk = blockIdx.x;
    const int d = threadIdx.x;
    const size_t l0 = (size_t)blk * 64;

    for (int t = d; t < 64 * 16; t += 512) {
        int r = t >> 4, c = t & 15;
        Cs[r][c] = ((const float4*)Cm)[(l0 + r) * 16 + c];
    }
    __syncthreads();

    ull PS2[32];
    #pragma unroll
    for (int q = 0; q < 32; q++)
        PS2[q] = pack2(ps[((size_t)blk * 64 + 2 * q) * 512 + d],
                       ps[((size_t)blk * 64 + 2 * q + 1) * 512 + d]);
    const float dsk = Dskip[d];

    #pragma unroll 1
    for (int i = 0; i < 64; i++) {
        const size_t m = l0 + i;
        const ull* Cp = (const ull*)&Cs[i][0];
        ull y2 = 0ull;
        #pragma unroll
        for (int q = 0; q < 32; q++)
            FMA2_ACC(y2, Cp[q], PS2[q]);
        float ylo, yhi; unpack2(y2, ylo, yhi);
        Y[m * 512 + d] = Y[m * 512 + d] + decay[m * 512 + d] * (ylo + yhi)
                         + dsk * xp[m * 1024 + d];
    }
}

// h = tf32round(rmsnorm(y, g) * silu(z)), in place over Y.
__global__ void outnorm_k(float* __restrict__ Y, const float* __restrict__ xp,
                          const float* __restrict__ g)
{
    __shared__ float red[256];
    const int m = blockIdx.x;
    const int t = threadIdx.x;
    float v0 = Y[(size_t)m * 512 + t];
    float v1 = Y[(size_t)m * 512 + t + 256];
    red[t] = v0 * v0 + v1 * v1;
    __syncthreads();
    for (int s = 128; s > 0; s >>= 1) {
        if (t < s) red[t] += red[t + s];
        __syncthreads();
    }
    float rs = rsqrtf(red[0] * (1.0f / 512.0f) + 1e-6f);
    float z0 = xp[(size_t)m * 1024 + 512 + t];
    float z1 = xp[(size_t)m * 1024 + 512 + t + 256];
    float s0 = z0 / (1.0f + expf(-z0));
    float s1 = z1 / (1.0f + expf(-z1));
    Y[(size_t)m * 512 + t]       = __uint_as_float(f2tf32(v0 * rs * g[t] * s0));
    Y[(size_t)m * 512 + t + 256] = __uint_as_float(f2tf32(v1 * rs * g[t + 256] * s1));
}

// ============================ launch ============================
#define GEMM_SMEM 73728

extern "C" void kernel_launch(void* const* d_in, const int* in_sizes, int n_in,
                              void* d_out, int out_size)
{
    const float* x       = (const float*)d_in[0];
    const float* A_log   = (const float*)d_in[1];
    const float* dt_bias = (const float*)d_in[2];
    const float* D_skip  = (const float*)d_in[3];
    const float* W_xproj = (const float*)d_in[4];
    const float* b_xproj = (const float*)d_in[5];
    const float* W_B     = (const float*)d_in[6];
    const float* W_C     = (const float*)d_in[7];
    const float* W_dt    = (const float*)d_in[8];
    const float* g_Bn    = (const float*)d_in[9];
    const float* g_Cn    = (const float*)d_in[10];
    const float* g_on    = (const float*)d_in[11];
    const float* W_out   = (const float*)d_in[12];
    const float* b_out   = (const float*)d_in[13];
    float* out = (float*)d_out;

    float *p_xp, *p_xt, *p_xbt, *p_Bm, *p_Cm, *p_ax, *p_Y, *p_cs, *p_dt, *p_Ac;
    float *p_Wxp, *p_Wdt, *p_Wout, *p_Wbc;
    cudaGetSymbolAddress((void**)&p_xp,  g_xp);
    cudaGetSymbolAddress((void**)&p_xt,  g_xt);
    cudaGetSymbolAddress((void**)&p_xbt, g_xbt);
    cudaGetSymbolAddress((void**)&p_Bm,  g_Bm);
    cudaGetSymbolAddress((void**)&p_Cm,  g_Cm);
    cudaGetSymbolAddress((void**)&p_ax,  g_ax);
    cudaGetSymbolAddress((void**)&p_Y,   g_Yb);
    cudaGetSymbolAddress((void**)&p_cs,  g_cs);
    cudaGetSymbolAddress((void**)&p_dt,  g_dtot);
    cudaGetSymbolAddress((void**)&p_Ac,  g_Ac);
    cudaGetSymbolAddress((void**)&p_Wxp,  g_Wt_xp);
    cudaGetSymbolAddress((void**)&p_Wdt,  g_Wt_dt);
    cudaGetSymbolAddress((void**)&p_Wout, g_Wt_out);
    cudaGetSymbolAddress((void**)&p_Wbc,  g_Wt_bc);

    cudaFuncSetAttribute(mma_gemm_k<0>, cudaFuncAttributeMaxDynamicSharedMemorySize, GEMM_SMEM);
    cudaFuncSetAttribute(mma_gemm_k<1>, cudaFuncAttributeMaxDynamicSharedMemorySize, GEMM_SMEM);
    cudaFuncSetAttribute(mma_gemm_k<2>, cudaFuncAttributeMaxDynamicSharedMemorySize, GEMM_SMEM);
    cudaFuncSetAttribute(mma_gemm_k<3>, cudaFuncAttributeMaxDynamicSharedMemorySize, GEMM_SMEM);

    // 0: A coefficient
    acoef_k<<<1, 512>>>(A_log, p_Ac);
    // 1: weight transposes + x rounding
    prep_k<<<9280, 256>>>(x, W_xproj, W_dt, W_out, W_B, W_C,
                          p_xt, p_Wxp, p_Wdt, p_Wout, p_Wbc);
    // 2: xp = x @ W_xproj + b_xproj (also emits tf32-rounded x_bar)
    mma_gemm_k<3><<<dim3(8, 128), 256, GEMM_SMEM>>>(
        p_xt, 512, p_Wxp, b_xproj, p_xp, p_xbt, 1024, nullptr, nullptr);
    // 3: fused B|C projection + rmsnorm
    mma_gemm_k<2><<<dim3(1, 128), 256, GEMM_SMEM>>>(
        p_xbt, 512, p_Wbc, nullptr, p_Bm, p_Cm, 64, g_Bn, g_Cn);
    // 4: a = exp(clip(clip(softplus(x_bar@W_dt + dt_bias),1e-4,5)*A, -18.42, 0))
    mma_gemm_k<1><<<dim3(4, 128), 256, GEMM_SMEM>>>(
        p_xbt, 512, p_Wdt, dt_bias, p_ax, nullptr, 512, p_Ac, nullptr);
    // 5: intra-chunk recurrence  (ncu capture target)
    scan_intra_k<<<NBLK, 512>>>(p_xp, p_Bm, p_Cm, p_ax, p_Y, p_cs, p_dt);
    // 6: inter-chunk state scan
    state_scan_k<<<(BQ * NQ * 128) / 256, 256>>>(p_cs, p_dt);
    // 7: y += decay * (C @ prev_state) + D_skip * x_bar
    yinter_k<<<NBLK, 512>>>(p_Cm, p_cs, p_ax, p_xp, D_skip, p_Y);
    // 8: h = rmsnorm(y) * silu(z) (tf32-rounded)
    outnorm_k<<<MQ, 256>>>(p_Y, p_xp, g_on);
    // 9: out = h @ W_out + b_out
    mma_gemm_k<0><<<dim3(4, 128), 256, GEMM_SMEM>>>(
        p_Y, 512, p_Wout, b_out, out, nullptr, 512, nullptr, nullptr);
}